// round 7
// baseline (speedup 1.0000x reference)
#include <cuda_runtime.h>

// Problem constants (T=512, B=32, A=64, N=128, H=8)
#define TPB   256
#define ADIM  64
#define NDIM  128
#define HDIM  8
#define TILES 4     // (t,b) pairs per block -> amortize weight LDS 4x

__global__ __launch_bounds__(TPB, 3)
void attn_fused_kernel(const float* __restrict__ agent,
                       const float* __restrict__ Wq, const float* __restrict__ bq,
                       const float* __restrict__ Wk, const float* __restrict__ bk,
                       float* __restrict__ out)
{
    __shared__ float sW[2][HDIM][NDIM];     // [0]=Wq^T, [1]=Wk^T  (sW[m][h][n])
    __shared__ float sb[2][HDIM];           // [0]=bq, [1]=bk
    __shared__ float qsm[TILES][ADIM * HDIM];   // q[a][h] at a*8+h
    __shared__ float ksm[TILES][ADIM * HDIM];   // k flat row-major; att reads ksm[h*64+a]

    const int tid = threadIdx.x;
    const long long tb0 = (long long)blockIdx.x * TILES;

    // ---- weights (transposed) + biases into smem ----
    for (int i = tid; i < NDIM * HDIM; i += TPB) {
        int n = i >> 3, h = i & 7;
        sW[0][h][n] = Wq[i];
        sW[1][h][n] = Wk[i];
    }
    if (tid < HDIM)      sb[0][tid] = bq[tid];
    else if (tid < 2*HDIM) sb[1][tid - HDIM] = bk[tid - HDIM];
    __syncthreads();

    // =========== phase 1: fused Q/K projection for 4 tiles ===========
    // thread = (row, N-half, mat): one matrix, 8 h-dots over N/2, 4 tiles.
    // acc[4][8] = 32 regs (vs 64 before) -> higher occupancy.
    {
        const int r   = tid >> 2;        // agent row 0..63
        const int c2  = tid & 1;         // N-half 0..1  (lane bit 0)
        const int mat = (tid >> 1) & 1;  // 0 = q, 1 = k (lane bit 1)

        const float4* srow[TILES];
        #pragma unroll
        for (int t = 0; t < TILES; t++)
            srow[t] = reinterpret_cast<const float4*>(
                agent + (tb0 + t) * (long long)(ADIM * NDIM) + (long long)r * NDIM);

        float acc[TILES][HDIM];
        #pragma unroll
        for (int t = 0; t < TILES; t++)
            #pragma unroll
            for (int h = 0; h < HDIM; h++) acc[t][h] = 0.f;

        const int cbase = c2 * 16;       // float4 index base of this N-half

        #pragma unroll 2
        for (int k = 0; k < 16; k++) {
            float4 s[TILES];
            #pragma unroll
            for (int t = 0; t < TILES; t++) s[t] = srow[t][cbase + k];

            const int nb = (cbase + k) * 4;
            #pragma unroll
            for (int h = 0; h < HDIM; h++) {
                const float4 w = *reinterpret_cast<const float4*>(&sW[mat][h][nb]);
                #pragma unroll
                for (int t = 0; t < TILES; t++)
                    acc[t][h] += s[t].x * w.x + s[t].y * w.y + s[t].z * w.z + s[t].w * w.w;
            }
        }

        // single butterfly stage: partner (xor 1) has the other N-half.
        // c2=0 lane keeps h0..3, c2=1 lane keeps h4..7.
        const int hbase = c2 * 4;
        #pragma unroll
        for (int t = 0; t < TILES; t++) {
            float* dst = mat ? ksm[t] : qsm[t];
            #pragma unroll
            for (int i = 0; i < 4; i++) {
                float sent = c2 ? acc[t][i] : acc[t][i + 4];
                float recv = __shfl_xor_sync(0xffffffffu, sent, 1);
                float f = (c2 ? acc[t][i + 4] : acc[t][i]) + recv;
                dst[r * HDIM + hbase + i] = f + sb[mat][hbase + i];
            }
        }
    }
    __syncthreads();

    // =========== phase 2: logits + softmax + off-diag store ===========
    // thread = (row-pair, 8-column chunk)
    {
        const int rp = tid >> 3;        // 0..31
        const int cc = tid & 7;         // column chunk 0..7
        const int r0 = rp * 2, r1 = r0 + 1;

        #pragma unroll
        for (int t = 0; t < TILES; t++) {
            float q0[HDIM], q1[HDIM];
            {
                float4 a = *reinterpret_cast<const float4*>(&qsm[t][r0 * HDIM]);
                float4 b = *reinterpret_cast<const float4*>(&qsm[t][r0 * HDIM + 4]);
                q0[0]=a.x; q0[1]=a.y; q0[2]=a.z; q0[3]=a.w;
                q0[4]=b.x; q0[5]=b.y; q0[6]=b.z; q0[7]=b.w;
                float4 e = *reinterpret_cast<const float4*>(&qsm[t][r1 * HDIM]);
                float4 d = *reinterpret_cast<const float4*>(&qsm[t][r1 * HDIM + 4]);
                q1[0]=e.x; q1[1]=e.y; q1[2]=e.z; q1[3]=e.w;
                q1[4]=d.x; q1[5]=d.y; q1[6]=d.z; q1[7]=d.w;
            }

            float a0[8], a1[8];
            #pragma unroll
            for (int i = 0; i < 8; i++) { a0[i] = 0.f; a1[i] = 0.f; }

            // att[r][a] = sum_h q[r][h] * kflat[h*64 + a]  (reshape semantics)
            #pragma unroll
            for (int h = 0; h < HDIM; h++) {
                const float4 ka = *reinterpret_cast<const float4*>(&ksm[t][h * ADIM + cc * 8]);
                const float4 kb = *reinterpret_cast<const float4*>(&ksm[t][h * ADIM + cc * 8 + 4]);
                const float x0 = q0[h], x1 = q1[h];
                a0[0] += x0 * ka.x; a0[1] += x0 * ka.y; a0[2] += x0 * ka.z; a0[3] += x0 * ka.w;
                a0[4] += x0 * kb.x; a0[5] += x0 * kb.y; a0[6] += x0 * kb.z; a0[7] += x0 * kb.w;
                a1[0] += x1 * ka.x; a1[1] += x1 * ka.y; a1[2] += x1 * ka.z; a1[3] += x1 * ka.w;
                a1[4] += x1 * kb.x; a1[5] += x1 * kb.y; a1[6] += x1 * kb.z; a1[7] += x1 * kb.w;
            }

            // softmax over 64 cols: 8 local + reduce over the 8 lanes of this row-pair
            float m0 = a0[0], m1 = a1[0];
            #pragma unroll
            for (int i = 1; i < 8; i++) { m0 = fmaxf(m0, a0[i]); m1 = fmaxf(m1, a1[i]); }
            #pragma unroll
            for (int s = 1; s < 8; s <<= 1) {
                m0 = fmaxf(m0, __shfl_xor_sync(0xffffffffu, m0, s));
                m1 = fmaxf(m1, __shfl_xor_sync(0xffffffffu, m1, s));
            }
            float s0 = 0.f, s1 = 0.f;
            #pragma unroll
            for (int i = 0; i < 8; i++) {
                a0[i] = __expf(a0[i] - m0); s0 += a0[i];
                a1[i] = __expf(a1[i] - m1); s1 += a1[i];
            }
            #pragma unroll
            for (int s = 1; s < 8; s <<= 1) {
                s0 += __shfl_xor_sync(0xffffffffu, s0, s);
                s1 += __shfl_xor_sync(0xffffffffu, s1, s);
            }
            const float inv0 = __frcp_rn(s0);
            const float inv1 = __frcp_rn(s1);

            // off-diagonal gather store: col a -> a (a<r) / a-1 (a>r), skip a==r
            const long long tb = tb0 + t;
            float* o0 = out + (tb * ADIM + r0) * (long long)(ADIM - 1);
            float* o1 = out + (tb * ADIM + r1) * (long long)(ADIM - 1);
            #pragma unroll
            for (int i = 0; i < 8; i++) {
                const int a = cc * 8 + i;
                if (a != r0) o0[a - (a > r0 ? 1 : 0)] = a0[i] * inv0;
                if (a != r1) o1[a - (a > r1 ? 1 : 0)] = a1[i] * inv1;
            }
        }
    }
}

extern "C" void kernel_launch(void* const* d_in, const int* in_sizes, int n_in,
                              void* d_out, int out_size)
{
    const float* agent = (const float*)d_in[0];
    const float* Wq    = (const float*)d_in[1];
    const float* bq    = (const float*)d_in[2];
    const float* Wk    = (const float*)d_in[3];
    const float* bk    = (const float*)d_in[4];
    float* out = (float*)d_out;

    const int T = 512, B = 32;
    attn_fused_kernel<<<(T * B) / TILES, TPB>>>(agent, Wq, bq, Wk, bk, out);
}